// round 1
// baseline (speedup 1.0000x reference)
#include <cuda_runtime.h>
#include <cstdint>

#define RES 64
#define CH 32
#define DIM 512
#define BATCH 32
#define M_TOTAL (RES*RES*CH)      /* 131072 */
#define MTILE 128
#define KC 16
#define NCHUNK (DIM/KC)           /* 32 */
#define SU_PAD 20                 /* words per sU row (16B-aligned, conflict-engineered) */
#define NTHREADS 64

// scaledT[k][b] = L[k] * style[b][k]
__device__ float g_scaled[DIM * BATCH];

__global__ void prep_kernel(const float* __restrict__ style, const float* __restrict__ L) {
    int i = blockIdx.x * blockDim.x + threadIdx.x;   // i = k*32 + b
    if (i < DIM * BATCH) {
        int k = i >> 5, b = i & 31;
        g_scaled[i] = L[k] * style[b * DIM + k];
    }
}

__device__ __forceinline__ void ffma2(unsigned long long &d, unsigned long long a, unsigned long long b) {
    asm volatile("fma.rn.f32x2 %0, %1, %2, %0;" : "+l"(d) : "l"(a), "l"(b));
}
__device__ __forceinline__ unsigned long long dup2(float x) {
    unsigned long long r;
    asm("mov.b64 %0, {%1, %1};" : "=l"(r) : "f"(x));
    return r;
}
__device__ __forceinline__ void unpack2(unsigned long long v, float &lo, float &hi) {
    asm("mov.b64 {%0, %1}, %2;" : "=f"(lo), "=f"(hi) : "l"(v));
}
__device__ __forceinline__ void cp16(uint32_t dst, const void* src) {
    asm volatile("cp.async.cg.shared.global [%0], [%1], 16;" :: "r"(dst), "l"(src));
}
__device__ __forceinline__ void cp_commit() {
    asm volatile("cp.async.commit_group;" ::: "memory");
}
__device__ __forceinline__ void cp_wait1() {
    asm volatile("cp.async.wait_group 1;" ::: "memory");
}

__global__ void __launch_bounds__(NTHREADS, 7)
gemm_kernel(const float* __restrict__ U, const float* __restrict__ mu, float* __restrict__ out)
{
    __shared__ float sU[2][MTILE][SU_PAD];      // 20480 B
    __shared__ float sS[2][KC][BATCH];          //  4096 B

    const int tx = threadIdx.x;
    const int mq = tx >> 2;      // 0..15 -> owns m = mq + 16*r, r=0..7
    const int bq = tx & 3;       // 0..3  -> owns b = bq*8 .. bq*8+7
    const int mbase = blockIdx.x * MTILE;

    const uint32_t su_base = (uint32_t)__cvta_generic_to_shared(&sU[0][0][0]);
    const uint32_t ss_base = (uint32_t)__cvta_generic_to_shared(&sS[0][0][0]);

    // ---- prefetch one K-chunk (c) into buffer (buf) via cp.async ----
    auto prefetch = [&](int c, int buf) {
        const float* ubase = U + (size_t)mbase * DIM + c * KC;
        #pragma unroll
        for (int j = 0; j < 8; ++j) {
            int id  = j * NTHREADS + tx;   // 0..511 : 128 rows x 4 segs of 16B
            int row = id >> 2;
            int kq  = id & 3;
            uint32_t dst = su_base + (uint32_t)(((buf * MTILE + row) * SU_PAD + kq * 4) * 4);
            cp16(dst, ubase + (size_t)row * DIM + kq * 4);
        }
        // scaled chunk: contiguous 2048B copy
        const float* sbase = g_scaled + c * KC * BATCH;
        #pragma unroll
        for (int j = 0; j < 2; ++j) {
            int seg = j * NTHREADS + tx;   // 0..127 segs of 16B
            uint32_t dst = ss_base + (uint32_t)((buf * KC * BATCH + seg * 4) * 4);
            cp16(dst, sbase + seg * 4);
        }
    };

    unsigned long long acc[8][4];
    #pragma unroll
    for (int r = 0; r < 8; ++r)
        #pragma unroll
        for (int p = 0; p < 4; ++p) acc[r][p] = 0ull;

    prefetch(0, 0); cp_commit();
    prefetch(1, 1); cp_commit();

    for (int c = 0; c < NCHUNK; ++c) {
        cp_wait1();
        __syncthreads();
        const int buf = c & 1;

        #pragma unroll
        for (int k = 0; k < KC; ++k) {
            // scaled pairs for this thread's 8 b's (consecutive, 16B aligned)
            ulonglong2 sp0 = *(const ulonglong2*)&sS[buf][k][bq * 8];
            ulonglong2 sp1 = *(const ulonglong2*)&sS[buf][k][bq * 8 + 4];
            #pragma unroll
            for (int r = 0; r < 8; ++r) {
                float u = sU[buf][mq + 16 * r][k];
                unsigned long long u2 = dup2(u);
                ffma2(acc[r][0], u2, sp0.x);
                ffma2(acc[r][1], u2, sp0.y);
                ffma2(acc[r][2], u2, sp1.x);
                ffma2(acc[r][3], u2, sp1.y);
            }
        }

        __syncthreads();
        if (c + 2 < NCHUNK) prefetch(c + 2, buf);
        cp_commit();   // empty group near the tail keeps wait_group accounting simple
    }

    // ---- epilogue: add mu, scatter to out[b][m] ----
    #pragma unroll
    for (int r = 0; r < 8; ++r) {
        int m = mbase + mq + 16 * r;
        float muv = __ldg(&mu[m]);
        #pragma unroll
        for (int p = 0; p < 4; ++p) {
            float lo, hi;
            unpack2(acc[r][p], lo, hi);
            int b = bq * 8 + p * 2;
            out[(size_t)b       * M_TOTAL + m] = lo + muv;
            out[(size_t)(b + 1) * M_TOTAL + m] = hi + muv;
        }
    }
}

extern "C" void kernel_launch(void* const* d_in, const int* in_sizes, int n_in,
                              void* d_out, int out_size) {
    // Identify inputs robustly by element count
    const float *style = nullptr, *U = nullptr, *L = nullptr, *mu = nullptr;
    for (int i = 0; i < n_in; ++i) {
        switch (in_sizes[i]) {
            case BATCH * DIM:        style = (const float*)d_in[i]; break;  // 16384
            case M_TOTAL * DIM:      U     = (const float*)d_in[i]; break;  // 67108864
            case DIM:                L     = (const float*)d_in[i]; break;  // 512
            case M_TOTAL:            mu    = (const float*)d_in[i]; break;  // 131072
            default: break;
        }
    }
    float* out = (float*)d_out;

    prep_kernel<<<(DIM * BATCH + 255) / 256, 256>>>(style, L);
    gemm_kernel<<<M_TOTAL / MTILE, NTHREADS>>>(U, mu, out);
}

// round 3
// speedup vs baseline: 1.8369x; 1.8369x over previous
#include <cuda_runtime.h>
#include <cstdint>

#define DIM 512
#define BATCH 32
#define M_TOTAL 131072            /* 64*64*32 */
#define MTILE 128
#define KC 32                      /* k per chunk */
#define NCHUNK (DIM/KC)            /* 16 */
#define NTHREADS 128
#define A_STRIDE 36                /* words per A smem row: banks (4g+tg)%32 bijective */
#define B_STRIDE 40                /* words per B smem row: banks (8tg+g)%32 bijective */

/* B operand, tf32-RNE: g_scaled[k*32+b] = rna_tf32(L[k]*style[b][k])  (k-major!) */
__device__ uint32_t g_scaled[DIM * BATCH];

__global__ void prep_kernel(const float* __restrict__ style, const float* __restrict__ L) {
    int i = blockIdx.x * blockDim.x + threadIdx.x;
    if (i < DIM * BATCH) {
        int k = i >> 5, b = i & 31;
        float v = L[k] * style[b * DIM + k];
        uint32_t bits;
        asm("cvt.rna.tf32.f32 %0, %1;" : "=r"(bits) : "f"(v));
        g_scaled[i] = bits;
    }
}

__device__ __forceinline__ uint32_t smem_u32(const void* p) {
    return (uint32_t)__cvta_generic_to_shared(p);
}
__device__ __forceinline__ void cp16(uint32_t dst, const void* src) {
    asm volatile("cp.async.cg.shared.global [%0], [%1], 16;" :: "r"(dst), "l"(src));
}
__device__ __forceinline__ void cp_commit() {
    asm volatile("cp.async.commit_group;" ::: "memory");
}
__device__ __forceinline__ void cp_wait1() {
    asm volatile("cp.async.wait_group 1;" ::: "memory");
}
__device__ __forceinline__ void mma_tf32(float* d, const uint32_t* a, const uint32_t* b) {
    asm volatile(
        "mma.sync.aligned.m16n8k8.row.col.f32.tf32.tf32.f32 "
        "{%0,%1,%2,%3}, {%4,%5,%6,%7}, {%8,%9}, {%0,%1,%2,%3};"
        : "+f"(d[0]), "+f"(d[1]), "+f"(d[2]), "+f"(d[3])
        : "r"(a[0]), "r"(a[1]), "r"(a[2]), "r"(a[3]), "r"(b[0]), "r"(b[1]));
}

__global__ void __launch_bounds__(NTHREADS, 4)
gemm_kernel(const float* __restrict__ U, const float* __restrict__ mu, float* __restrict__ out)
{
    __shared__ uint32_t sA[2][MTILE * A_STRIDE];   /* 2 x 18 KB */
    __shared__ uint32_t sB[2][KC * B_STRIDE];      /* 2 x  5 KB */

    const int tid = threadIdx.x;
    const int wid = tid >> 5;
    const int lid = tid & 31;
    const int g   = lid >> 2;      /* groupID 0..7 */
    const int tg  = lid & 3;       /* thread-in-group 0..3 */
    const int mbase = blockIdx.x * MTILE;

    auto prefetch = [&](int c, int buf) {
        /* A: 128 rows x 128 B (k-contiguous), fully coalesced 16B lanes */
        const float* ubase = U + (size_t)mbase * DIM + c * KC;
        uint32_t adst = smem_u32(&sA[buf][0]);
        #pragma unroll
        for (int j = 0; j < 8; ++j) {
            int id  = j * NTHREADS + tid;
            int row = id >> 3, seg = id & 7;
            cp16(adst + (uint32_t)(row * (A_STRIDE * 4) + seg * 16),
                 ubase + (size_t)row * DIM + seg * 4);
        }
        /* B: 32 k-rows x 128 B */
        const uint32_t* bsrc = g_scaled + c * KC * BATCH;
        uint32_t bdst = smem_u32(&sB[buf][0]);
        #pragma unroll
        for (int j = 0; j < 2; ++j) {
            int id  = j * NTHREADS + tid;
            int row = id >> 3, seg = id & 7;
            cp16(bdst + (uint32_t)(row * (B_STRIDE * 4) + seg * 16),
                 bsrc + (size_t)row * BATCH + seg * 4);
        }
    };

    float acc[2][4][4];
    #pragma unroll
    for (int mt = 0; mt < 2; ++mt)
        #pragma unroll
        for (int nt = 0; nt < 4; ++nt)
            #pragma unroll
            for (int r = 0; r < 4; ++r) acc[mt][nt][r] = 0.0f;

    prefetch(0, 0); cp_commit();
    prefetch(1, 1); cp_commit();

    for (int c = 0; c < NCHUNK; ++c) {
        cp_wait1();
        __syncthreads();
        const uint32_t* A = sA[c & 1];
        const uint32_t* B = sB[c & 1];

        #pragma unroll
        for (int ks = 0; ks < 4; ++ks) {
            uint32_t a[2][4], b[4][2];
            #pragma unroll
            for (int mt = 0; mt < 2; ++mt) {
                int rb = wid * 32 + mt * 16;
                /* +0x1000: round-to-nearest into tf32 (HW drops low 13 bits) */
                a[mt][0] = A[(rb + g)     * A_STRIDE + ks * 8 + tg]     + 0x1000u;
                a[mt][1] = A[(rb + g + 8) * A_STRIDE + ks * 8 + tg]     + 0x1000u;
                a[mt][2] = A[(rb + g)     * A_STRIDE + ks * 8 + tg + 4] + 0x1000u;
                a[mt][3] = A[(rb + g + 8) * A_STRIDE + ks * 8 + tg + 4] + 0x1000u;
            }
            #pragma unroll
            for (int nt = 0; nt < 4; ++nt) {
                b[nt][0] = B[(ks * 8 + tg)     * B_STRIDE + nt * 8 + g];
                b[nt][1] = B[(ks * 8 + tg + 4) * B_STRIDE + nt * 8 + g];
            }
            #pragma unroll
            for (int mt = 0; mt < 2; ++mt)
                #pragma unroll
                for (int nt = 0; nt < 4; ++nt)
                    mma_tf32(acc[mt][nt], a[mt], b[nt]);
        }

        __syncthreads();
        if (c + 2 < NCHUNK) prefetch(c + 2, c & 1);
        cp_commit();   /* possibly-empty group keeps wait_group accounting simple */
    }

    /* epilogue: D[g][2tg], D[g][2tg+1], D[g+8][...]; add mu, store out[b][m] */
    #pragma unroll
    for (int mt = 0; mt < 2; ++mt) {
        int m0 = mbase + wid * 32 + mt * 16 + g;
        float mu0 = __ldg(&mu[m0]);
        float mu1 = __ldg(&mu[m0 + 8]);
        #pragma unroll
        for (int nt = 0; nt < 4; ++nt) {
            int b0 = nt * 8 + 2 * tg;
            out[(size_t)b0       * M_TOTAL + m0]     = acc[mt][nt][0] + mu0;
            out[(size_t)(b0 + 1) * M_TOTAL + m0]     = acc[mt][nt][1] + mu0;
            out[(size_t)b0       * M_TOTAL + m0 + 8] = acc[mt][nt][2] + mu1;
            out[(size_t)(b0 + 1) * M_TOTAL + m0 + 8] = acc[mt][nt][3] + mu1;
        }
    }
}

extern "C" void kernel_launch(void* const* d_in, const int* in_sizes, int n_in,
                              void* d_out, int out_size) {
    const float *style = nullptr, *U = nullptr, *L = nullptr, *mu = nullptr;
    for (int i = 0; i < n_in; ++i) {
        switch (in_sizes[i]) {
            case BATCH * DIM:   style = (const float*)d_in[i]; break;
            case M_TOTAL * DIM: U     = (const float*)d_in[i]; break;
            case DIM:           L     = (const float*)d_in[i]; break;
            case M_TOTAL:       mu    = (const float*)d_in[i]; break;
            default: break;
        }
    }
    float* out = (float*)d_out;

    prep_kernel<<<(BATCH * DIM + 255) / 256, 256>>>(style, L);
    gemm_kernel<<<M_TOTAL / MTILE, NTHREADS>>>(U, mu, out);
}